// round 8
// baseline (speedup 1.0000x reference)
#include <cuda_runtime.h>
#include <cuda_bf16.h>
#include <math.h>
#include <stdint.h>

// Problem constants
#define B_  4
#define L_  2048
#define D_  1024
#define H_  16
#define KD_ 64
#define M_  (B_ * L_)        // 8192 token rows
#define EPS_ 1e-5f

// ---------------- scratch (device globals; no allocation allowed) ----------
__device__ float g_q[M_ * D_];
__device__ float g_k[M_ * D_];
__device__ float g_v[M_ * D_];
__device__ float g_o[M_ * D_];
__device__ float g_res[M_ * D_];
__device__ float g_qr[M_ * D_];     // tf32-rounded copy of queries (MMA operand)
__device__ float g_wqt[D_ * D_];
__device__ float g_wkt[D_ * D_];
__device__ float g_wvt[D_ * D_];
__device__ float g_wot[D_ * D_];

// ---------------- helpers ---------------------------------------------------
__device__ __forceinline__ float tf32r(float x) {
    uint32_t u;
    asm("cvt.rna.tf32.f32 %0, %1;" : "=r"(u) : "f"(x));
    return __uint_as_float(u);
}

__device__ __forceinline__ void mma_tf32_4(float* d,
    uint32_t a0, uint32_t a1, uint32_t a2, uint32_t a3,
    uint32_t b0, uint32_t b1) {
    asm volatile(
        "mma.sync.aligned.m16n8k8.row.col.f32.tf32.tf32.f32 "
        "{%0,%1,%2,%3}, {%4,%5,%6,%7}, {%8,%9}, {%0,%1,%2,%3};\n"
        : "+f"(d[0]), "+f"(d[1]), "+f"(d[2]), "+f"(d[3])
        : "r"(a0), "r"(a1), "r"(a2), "r"(a3), "r"(b0), "r"(b1));
}

__device__ __forceinline__ uint32_t smem_u32(const void* p) {
    uint32_t a;
    asm("{ .reg .u64 t; cvta.to.shared.u64 t, %1; cvt.u32.u64 %0, t; }"
        : "=r"(a) : "l"(p));
    return a;
}
#define CP_ASYNC16(dst_u32, src_ptr) \
    asm volatile("cp.async.cg.shared.global [%0], [%1], 16;" \
        :: "r"(dst_u32), "l"(src_ptr))
#define CP_COMMIT() asm volatile("cp.async.commit_group;" ::: "memory")
#define CP_WAIT_ALL() asm volatile("cp.async.wait_all;" ::: "memory")

// ================= tf32 warp-MMA GEMM ======================================
// C[8192,1024] = A@Bt^T + bias (+Res).  Tile 128x128, BK=32, 8 warps (2x4).
// k-permuted fragments: within each k8 block, a thread's register pair holds
// contraction indices (2ql, 2ql+1) for BOTH operands -> LDS.64 fragment
// loads.  Stride 40 == 8 (mod 32) => banks (8*qr + 2*ql) % 32 distinct per
// 16-lane phase: conflict-free.
#define GSTRIDE 40   // smem row stride in floats

__global__ __launch_bounds__(256) void gemm_mma(
    const float* __restrict__ A, const float* __restrict__ Bt,
    const float* __restrict__ bias, const float* __restrict__ Res,
    float* __restrict__ C, int rnd)
{
    __shared__ __align__(16) float As[128 * GSTRIDE];
    __shared__ __align__(16) float Bs[128 * GSTRIDE];

    const int tid  = threadIdx.x;
    const int wid  = tid >> 5;
    const int lane = tid & 31;
    const int wm = wid & 1;
    const int wn = wid >> 1;
    const int qr = lane >> 2;
    const int ql = lane & 3;

    const int row0 = blockIdx.y * 128;
    const int col0 = blockIdx.x * 128;

    float acc[4][4][4];
#pragma unroll
    for (int i = 0; i < 4; i++)
#pragma unroll
        for (int j = 0; j < 4; j++)
#pragma unroll
            for (int r = 0; r < 4; r++) acc[i][j][r] = 0.f;

    int fr[4], fc[4];
    const float* Aptr[4]; const float* Bptr[4];
#pragma unroll
    for (int i = 0; i < 4; i++) {
        int f = i * 256 + tid;
        fr[i] = f >> 3;
        fc[i] = (f & 7) * 4;
        Aptr[i] = A  + (size_t)(row0 + fr[i]) * D_ + fc[i];
        Bptr[i] = Bt + (size_t)(col0 + fr[i]) * D_ + fc[i];
    }

    float4 pa[4], pb[4];
#pragma unroll
    for (int i = 0; i < 4; i++) {
        pa[i] = *(const float4*)(Aptr[i]);
        pb[i] = *(const float4*)(Bptr[i]);
    }

    const int mb0 = wm * 64;
    const int nb0 = wn * 32;

    for (int c = 0; c < D_ / 32; ++c) {
#pragma unroll
        for (int i = 0; i < 4; i++) {
            *(float4*)&As[fr[i] * GSTRIDE + fc[i]] = pa[i];
            *(float4*)&Bs[fr[i] * GSTRIDE + fc[i]] = pb[i];
        }
        __syncthreads();

        if (c + 1 < D_ / 32) {
            const int k0 = (c + 1) * 32;
#pragma unroll
            for (int i = 0; i < 4; i++) {
                pa[i] = *(const float4*)(Aptr[i] + k0);
                pb[i] = *(const float4*)(Bptr[i] + k0);
            }
        }

#pragma unroll
        for (int ks = 0; ks < 4; ++ks) {
            uint32_t af[4][4], bf[4][2];
#pragma unroll
            for (int mt = 0; mt < 4; ++mt) {
                int rb = (mb0 + mt * 16 + qr) * GSTRIDE + ks * 8 + 2 * ql;
                float2 lo = *(const float2*)&As[rb];                 // k = 2ql, 2ql+1
                float2 hi = *(const float2*)&As[rb + 8 * GSTRIDE];
                af[mt][0] = __float_as_uint(lo.x);
                af[mt][2] = __float_as_uint(lo.y);
                af[mt][1] = __float_as_uint(hi.x);
                af[mt][3] = __float_as_uint(hi.y);
            }
#pragma unroll
            for (int nt = 0; nt < 4; ++nt) {
                int rb = (nb0 + nt * 8 + qr) * GSTRIDE + ks * 8 + 2 * ql;
                float2 b = *(const float2*)&Bs[rb];
                bf[nt][0] = __float_as_uint(b.x);
                bf[nt][1] = __float_as_uint(b.y);
            }
#pragma unroll
            for (int mt = 0; mt < 4; ++mt)
#pragma unroll
                for (int nt = 0; nt < 4; ++nt)
                    mma_tf32_4(acc[mt][nt], af[mt][0], af[mt][1], af[mt][2], af[mt][3],
                               bf[nt][0], bf[nt][1]);
        }
        __syncthreads();
    }

#pragma unroll
    for (int mt = 0; mt < 4; ++mt) {
        int row_lo = row0 + mb0 + mt * 16 + qr;
#pragma unroll
        for (int nt = 0; nt < 4; ++nt) {
            int col = col0 + nb0 + nt * 8 + ql * 2;
            float2 bb = *(const float2*)&bias[col];
            size_t off_lo = (size_t)row_lo * D_ + col;
            size_t off_hi = off_lo + (size_t)8 * D_;
            float2 o_lo, o_hi;
            o_lo.x = acc[mt][nt][0] + bb.x;
            o_lo.y = acc[mt][nt][1] + bb.y;
            o_hi.x = acc[mt][nt][2] + bb.x;
            o_hi.y = acc[mt][nt][3] + bb.y;
            if (Res) {
                float2 r0 = *(const float2*)&Res[off_lo];
                float2 r1 = *(const float2*)&Res[off_hi];
                o_lo.x += r0.x; o_lo.y += r0.y;
                o_hi.x += r1.x; o_hi.y += r1.y;
            }
            if (rnd) {
                o_lo.x = tf32r(o_lo.x); o_lo.y = tf32r(o_lo.y);
                o_hi.x = tf32r(o_hi.x); o_hi.y = tf32r(o_hi.y);
            }
            *(float2*)&C[off_lo] = o_lo;
            *(float2*)&C[off_hi] = o_hi;
        }
    }
}

// ================ flash attention via tf32 mma.sync ========================
// Block: one (b,h), 128 query rows. 8 warps x 16 rows. KV tiles of 128 keys,
// double-buffered cp.async.
// K buffer stride 72 (== 8 mod 32): k-permuted float2 fragment loads for the
// S-phase, conflict-free.  V buffer stride 68: the PV scalar-load pattern
// (136*ql + qr) % 32 is conflict-free at 68 (2-way at 72), so V keeps 68.
// P@V uses the key-permutation trick: S-acc regs (c0,c2,c1,c3) form the A
// fragment directly when V's B-fragment reads keys (2ql, 2ql+1).
#define KST 72
#define VST 68
#define KTS (128 * KST)
#define VTS (128 * VST)

__global__ __launch_bounds__(256) void attn_mma(
    const float* __restrict__ Q, const float* __restrict__ K,
    const float* __restrict__ V, float* __restrict__ O)
{
    extern __shared__ float smf[];
    // layout: K0, V0, K1, V1
    float* kbuf[2] = { smf, smf + KTS + VTS };
    float* vbuf[2] = { smf + KTS, smf + 2 * KTS + VTS };

    const int bz = blockIdx.z, h = blockIdx.y;
    const int q0 = blockIdx.x * 128;
    const int tid = threadIdx.x, wid = tid >> 5, lane = tid & 31;
    const int qr = lane >> 2, ql = lane & 3;
    const int mrow = wid * 16;

    const float* Qg = Q + (((size_t)bz * L_ + q0) * H_ + h) * KD_;
    const float* Kg = K + (((size_t)bz * L_) * H_ + h) * KD_;
    const float* Vg = V + (((size_t)bz * L_) * H_ + h) * KD_;

    // ---- stage Q through kbuf[0], build pre-scaled k-permuted A frags ----
#pragma unroll
    for (int i = 0; i < 8; ++i) {
        int f = i * 256 + tid;
        int r = f >> 4, c4 = f & 15;
        *(float4*)&kbuf[0][r * KST + c4 * 4] =
            *(const float4*)(Qg + (size_t)r * (H_ * KD_) + c4 * 4);
    }
    __syncthreads();
    uint32_t qf[8][4];
#pragma unroll
    for (int ks = 0; ks < 8; ++ks) {
        int cl = ks * 8 + 2 * ql;
        qf[ks][0] = __float_as_uint(0.125f * kbuf[0][(mrow + qr) * KST + cl]);
        qf[ks][1] = __float_as_uint(0.125f * kbuf[0][(mrow + qr + 8) * KST + cl]);
        qf[ks][2] = __float_as_uint(0.125f * kbuf[0][(mrow + qr) * KST + cl + 1]);
        qf[ks][3] = __float_as_uint(0.125f * kbuf[0][(mrow + qr + 8) * KST + cl + 1]);
    }
    __syncthreads();

    float oacc[8][4];
#pragma unroll
    for (int nt = 0; nt < 8; ++nt)
#pragma unroll
        for (int r = 0; r < 4; ++r) oacc[nt][r] = 0.f;
    float m0 = -INFINITY, m1 = -INFINITY, l0 = 0.f, l1 = 0.f;

    // per-thread load slots (8 x float4 per operand per tile)
    int lr[8], lc[8];
#pragma unroll
    for (int i = 0; i < 8; ++i) {
        int f = i * 256 + tid;
        lr[i] = f >> 4;
        lc[i] = (f & 15) * 4;
    }

    // preload tile 0
    {
        uint32_t kd = smem_u32(kbuf[0]);
        uint32_t vd = smem_u32(vbuf[0]);
#pragma unroll
        for (int i = 0; i < 8; ++i) {
            size_t goff = (size_t)lr[i] * (H_ * KD_) + lc[i];
            CP_ASYNC16(kd + (uint32_t)(lr[i] * KST + lc[i]) * 4u, Kg + goff);
            CP_ASYNC16(vd + (uint32_t)(lr[i] * VST + lc[i]) * 4u, Vg + goff);
        }
        CP_COMMIT();
    }

    const int NT = L_ / 128;     // 16 kv tiles
    for (int t = 0; t < NT; ++t) {
        CP_WAIT_ALL();
        __syncthreads();
        if (t + 1 < NT) {
            const int nb = (t + 1) & 1;
            uint32_t kd = smem_u32(kbuf[nb]);
            uint32_t vd = smem_u32(vbuf[nb]);
            const float* Kn = Kg + (size_t)(t + 1) * 128 * (H_ * KD_);
            const float* Vn = Vg + (size_t)(t + 1) * 128 * (H_ * KD_);
#pragma unroll
            for (int i = 0; i < 8; ++i) {
                size_t goff = (size_t)lr[i] * (H_ * KD_) + lc[i];
                CP_ASYNC16(kd + (uint32_t)(lr[i] * KST + lc[i]) * 4u, Kn + goff);
                CP_ASYNC16(vd + (uint32_t)(lr[i] * VST + lc[i]) * 4u, Vn + goff);
            }
            CP_COMMIT();
        }
        const float* Kc = kbuf[t & 1];
        const float* Vc = vbuf[t & 1];

        // ---- S = (Q/8) @ K^T : 16 n-tiles of 8 keys, float2 B frags ----
        float sacc[16][4];
#pragma unroll
        for (int nt = 0; nt < 16; ++nt)
#pragma unroll
            for (int r = 0; r < 4; ++r) sacc[nt][r] = 0.f;
#pragma unroll
        for (int ks = 0; ks < 8; ++ks) {
#pragma unroll
            for (int nt = 0; nt < 16; ++nt) {
                int rb = (nt * 8 + qr) * KST + ks * 8 + 2 * ql;
                float2 b = *(const float2*)&Kc[rb];     // d = 2ql, 2ql+1
                mma_tf32_4(sacc[nt], qf[ks][0], qf[ks][1], qf[ks][2], qf[ks][3],
                           __float_as_uint(b.x), __float_as_uint(b.y));
            }
        }

        // ---- online softmax ----
        float tm0 = -INFINITY, tm1 = -INFINITY;
#pragma unroll
        for (int nt = 0; nt < 16; ++nt) {
            tm0 = fmaxf(tm0, fmaxf(sacc[nt][0], sacc[nt][1]));
            tm1 = fmaxf(tm1, fmaxf(sacc[nt][2], sacc[nt][3]));
        }
        tm0 = fmaxf(tm0, __shfl_xor_sync(0xffffffff, tm0, 1));
        tm0 = fmaxf(tm0, __shfl_xor_sync(0xffffffff, tm0, 2));
        tm1 = fmaxf(tm1, __shfl_xor_sync(0xffffffff, tm1, 1));
        tm1 = fmaxf(tm1, __shfl_xor_sync(0xffffffff, tm1, 2));

        float mn0 = fmaxf(m0, tm0), mn1 = fmaxf(m1, tm1);
        float c0 = __expf(m0 - mn0), c1 = __expf(m1 - mn1);
        l0 *= c0; l1 *= c1;
#pragma unroll
        for (int nt = 0; nt < 8; ++nt) {
            oacc[nt][0] *= c0; oacc[nt][1] *= c0;
            oacc[nt][2] *= c1; oacc[nt][3] *= c1;
        }
        m0 = mn0; m1 = mn1;

#pragma unroll
        for (int nt = 0; nt < 16; ++nt) {
            float p0 = __expf(sacc[nt][0] - m0);
            float p1 = __expf(sacc[nt][1] - m0);
            float p2 = __expf(sacc[nt][2] - m1);
            float p3 = __expf(sacc[nt][3] - m1);
            l0 += p0 + p1;
            l1 += p2 + p3;
            sacc[nt][0] = tf32r(p0);
            sacc[nt][1] = tf32r(p1);
            sacc[nt][2] = tf32r(p2);
            sacc[nt][3] = tf32r(p3);
        }

        // ---- O += P @ V (key-permuted B fragments) ----
#pragma unroll
        for (int g = 0; g < 16; ++g) {
            uint32_t a0 = __float_as_uint(sacc[g][0]);
            uint32_t a1 = __float_as_uint(sacc[g][2]);
            uint32_t a2 = __float_as_uint(sacc[g][1]);
            uint32_t a3 = __float_as_uint(sacc[g][3]);
#pragma unroll
            for (int nt = 0; nt < 8; ++nt) {
                uint32_t b0 = __float_as_uint(Vc[(g * 8 + 2 * ql) * VST + nt * 8 + qr]);
                uint32_t b1 = __float_as_uint(Vc[(g * 8 + 2 * ql + 1) * VST + nt * 8 + qr]);
                mma_tf32_4(oacc[nt], a0, a1, a2, a3, b0, b1);
            }
        }
    }

    // reduce the softmax denominator across the thread quad (each thread's l
    // only covers score columns (2ql, 2ql+1) of each 8-tile; oacc covers all)
    l0 += __shfl_xor_sync(0xffffffff, l0, 1);
    l0 += __shfl_xor_sync(0xffffffff, l0, 2);
    l1 += __shfl_xor_sync(0xffffffff, l1, 1);
    l1 += __shfl_xor_sync(0xffffffff, l1, 2);

    // ---- normalize + store (tf32-rounded for the Wo GEMM) ----
    float inv0 = 1.f / l0, inv1 = 1.f / l1;
    const int row_lo = q0 + mrow + qr;
    const int row_hi = row_lo + 8;
#pragma unroll
    for (int nt = 0; nt < 8; ++nt) {
        int d = nt * 8 + 2 * ql;
        float2 vlo, vhi;
        vlo.x = tf32r(oacc[nt][0] * inv0);
        vlo.y = tf32r(oacc[nt][1] * inv0);
        vhi.x = tf32r(oacc[nt][2] * inv1);
        vhi.y = tf32r(oacc[nt][3] * inv1);
        *(float2*)&O[(((size_t)bz * L_ + row_lo) * H_ + h) * KD_ + d] = vlo;
        *(float2*)&O[(((size_t)bz * L_ + row_hi) * H_ + h) * KD_ + d] = vhi;
    }
}

// ---------------- elementwise tf32 rounding pass ---------------------------
__global__ __launch_bounds__(256) void round_tf32_kernel(
    const float* __restrict__ X, float* __restrict__ Y)
{
    int i = blockIdx.x * 256 + threadIdx.x;
    float4 v = ((const float4*)X)[i];
    float4 o;
    o.x = tf32r(v.x); o.y = tf32r(v.y); o.z = tf32r(v.z); o.w = tf32r(v.w);
    ((float4*)Y)[i] = o;
}

// ---------------- weight transpose + tf32 round ----------------------------
__global__ __launch_bounds__(256) void transpose4(
    const float* __restrict__ W0, const float* __restrict__ W1,
    const float* __restrict__ W2, const float* __restrict__ W3,
    float* __restrict__ T0, float* __restrict__ T1,
    float* __restrict__ T2, float* __restrict__ T3)
{
    __shared__ float tile[32][33];
    const float* W; float* T;
    switch (blockIdx.z) {
        case 0: W = W0; T = T0; break;
        case 1: W = W1; T = T1; break;
        case 2: W = W2; T = T2; break;
        default: W = W3; T = T3; break;
    }
    int tx = threadIdx.x, ty = threadIdx.y;
    int x = blockIdx.x * 32 + tx;
    int y = blockIdx.y * 32 + ty;
#pragma unroll
    for (int i = 0; i < 4; ++i)
        tile[ty + 8 * i][tx] = W[(size_t)(y + 8 * i) * D_ + x];
    __syncthreads();
    int x2 = blockIdx.y * 32 + tx;
    int y2 = blockIdx.x * 32 + ty;
#pragma unroll
    for (int i = 0; i < 4; ++i)
        T[(size_t)(y2 + 8 * i) * D_ + x2] = tf32r(tile[tx][ty + 8 * i]);
}

// ---------------- LayerNorm: one block per row -----------------------------
__global__ __launch_bounds__(256) void ln_kernel(
    const float* __restrict__ X, const float* __restrict__ gamma,
    const float* __restrict__ beta, float* __restrict__ Y)
{
    const int row = blockIdx.x;
    const int tid = threadIdx.x;
    const float4* x = (const float4*)(X + (size_t)row * D_);
    float4 v = x[tid];

    float s  = v.x + v.y + v.z + v.w;
    float sq = v.x * v.x + v.y * v.y + v.z * v.z + v.w * v.w;
#pragma unroll
    for (int off = 16; off > 0; off >>= 1) {
        s  += __shfl_xor_sync(0xffffffff, s, off);
        sq += __shfl_xor_sync(0xffffffff, sq, off);
    }
    __shared__ float2 red[8];
    if ((tid & 31) == 0) red[tid >> 5] = make_float2(s, sq);
    __syncthreads();
    if (tid < 8) {
        float2 r = red[tid];
#pragma unroll
        for (int off = 4; off > 0; off >>= 1) {
            r.x += __shfl_xor_sync(0xff, r.x, off);
            r.y += __shfl_xor_sync(0xff, r.y, off);
        }
        if (tid == 0) red[0] = r;
    }
    __syncthreads();
    float mean = red[0].x * (1.f / D_);
    float var  = red[0].y * (1.f / D_) - mean * mean;
    float rstd = rsqrtf(var + EPS_);

    float4 g = ((const float4*)gamma)[tid];
    float4 bt = ((const float4*)beta)[tid];
    float4 o;
    o.x = (v.x - mean) * rstd * g.x + bt.x;
    o.y = (v.y - mean) * rstd * g.y + bt.y;
    o.z = (v.z - mean) * rstd * g.z + bt.z;
    o.w = (v.w - mean) * rstd * g.w + bt.w;
    ((float4*)(Y + (size_t)row * D_))[tid] = o;
}

// ---------------- host launch ----------------------------------------------
#define ATTN_SMEM (2 * (KTS + VTS) * 4)   // 143360 bytes

extern "C" void kernel_launch(void* const* d_in, const int* in_sizes, int n_in,
                              void* d_out, int out_size)
{
    const float* queries = (const float*)d_in[0];
    const float* Wq = (const float*)d_in[1];
    const float* bq = (const float*)d_in[2];
    const float* Wk = (const float*)d_in[3];
    const float* bk = (const float*)d_in[4];
    const float* Wv = (const float*)d_in[5];
    const float* bv = (const float*)d_in[6];
    const float* Wo = (const float*)d_in[7];
    const float* bo = (const float*)d_in[8];
    const float* gamma = (const float*)d_in[9];
    const float* beta  = (const float*)d_in[10];

    float *q, *k, *v, *o, *res, *qr, *wqt, *wkt, *wvt, *wot;
    cudaGetSymbolAddress((void**)&q,   g_q);
    cudaGetSymbolAddress((void**)&k,   g_k);
    cudaGetSymbolAddress((void**)&v,   g_v);
    cudaGetSymbolAddress((void**)&o,   g_o);
    cudaGetSymbolAddress((void**)&res, g_res);
    cudaGetSymbolAddress((void**)&qr,  g_qr);
    cudaGetSymbolAddress((void**)&wqt, g_wqt);
    cudaGetSymbolAddress((void**)&wkt, g_wkt);
    cudaGetSymbolAddress((void**)&wvt, g_wvt);
    cudaGetSymbolAddress((void**)&wot, g_wot);

    cudaFuncSetAttribute(attn_mma, cudaFuncAttributeMaxDynamicSharedMemorySize,
                         ATTN_SMEM);

    round_tf32_kernel<<<(M_ * D_) / (256 * 4), 256>>>(queries, qr);
    transpose4<<<dim3(32, 32, 4), dim3(32, 8)>>>(Wq, Wk, Wv, Wo, wqt, wkt, wvt, wot);

    dim3 gGrid(D_ / 128, M_ / 128);   // (8, 64)
    gemm_mma<<<gGrid, 256>>>(qr, wqt, bq, nullptr, q, 1);
    gemm_mma<<<gGrid, 256>>>(qr, wkt, bk, nullptr, k, 1);
    gemm_mma<<<gGrid, 256>>>(qr, wvt, bv, nullptr, v, 1);

    attn_mma<<<dim3(L_ / 128, H_, B_), 256, ATTN_SMEM>>>(q, k, v, o);

    gemm_mma<<<gGrid, 256>>>(o, wot, bo, queries, res, 0);

    ln_kernel<<<M_, 256>>>(res, gamma, beta, (float*)d_out);
}

// round 10
// speedup vs baseline: 1.0988x; 1.0988x over previous
#include <cuda_runtime.h>
#include <cuda_bf16.h>
#include <math.h>
#include <stdint.h>

// Problem constants
#define B_  4
#define L_  2048
#define D_  1024
#define H_  16
#define KD_ 64
#define M_  (B_ * L_)        // 8192 token rows
#define EPS_ 1e-5f

// ---------------- scratch (device globals; no allocation allowed) ----------
__device__ float g_q[M_ * D_];
__device__ float g_k[M_ * D_];
__device__ float g_v[M_ * D_];
__device__ float g_o[M_ * D_];
__device__ float g_res[M_ * D_];
__device__ float g_qr[M_ * D_];     // tf32-rounded copy of queries (MMA operand)
__device__ float g_wqt[D_ * D_];
__device__ float g_wkt[D_ * D_];
__device__ float g_wvt[D_ * D_];
__device__ float g_wot[D_ * D_];

// ---------------- helpers ---------------------------------------------------
__device__ __forceinline__ float tf32r(float x) {
    uint32_t u;
    asm("cvt.rna.tf32.f32 %0, %1;" : "=r"(u) : "f"(x));
    return __uint_as_float(u);
}

__device__ __forceinline__ void mma_tf32(float* d, const uint32_t* a, const uint32_t* b) {
    asm volatile(
        "mma.sync.aligned.m16n8k8.row.col.f32.tf32.tf32.f32 "
        "{%0,%1,%2,%3}, {%4,%5,%6,%7}, {%8,%9}, {%0,%1,%2,%3};\n"
        : "+f"(d[0]), "+f"(d[1]), "+f"(d[2]), "+f"(d[3])
        : "r"(a[0]), "r"(a[1]), "r"(a[2]), "r"(a[3]), "r"(b[0]), "r"(b[1]));
}

__device__ __forceinline__ void mma_tf32_4(float* d,
    uint32_t a0, uint32_t a1, uint32_t a2, uint32_t a3,
    uint32_t b0, uint32_t b1) {
    asm volatile(
        "mma.sync.aligned.m16n8k8.row.col.f32.tf32.tf32.f32 "
        "{%0,%1,%2,%3}, {%4,%5,%6,%7}, {%8,%9}, {%0,%1,%2,%3};\n"
        : "+f"(d[0]), "+f"(d[1]), "+f"(d[2]), "+f"(d[3])
        : "r"(a0), "r"(a1), "r"(a2), "r"(a3), "r"(b0), "r"(b1));
}

__device__ __forceinline__ uint32_t smem_u32(const void* p) {
    uint32_t a;
    asm("{ .reg .u64 t; cvta.to.shared.u64 t, %1; cvt.u32.u64 %0, t; }"
        : "=r"(a) : "l"(p));
    return a;
}
#define CP_ASYNC16(dst_u32, src_ptr) \
    asm volatile("cp.async.cg.shared.global [%0], [%1], 16;" \
        :: "r"(dst_u32), "l"(src_ptr))
#define CP_COMMIT() asm volatile("cp.async.commit_group;" ::: "memory")
#define CP_WAIT_ALL() asm volatile("cp.async.wait_all;" ::: "memory")

// ================= tf32 warp-MMA GEMM ======================================
// C[8192,1024] = A@Bt^T + bias (+Res).  Tile 128x128, BK=32, 8 warps (2x4).
// Round-7 proven configuration: scalar fragment LDS at stride 36, 128 regs,
// pinned to 2 CTAs/SM via launch bounds (the R8 float2 variant raised regs
// to 142 and halved occupancy -> regression).
#define GSTRIDE 36   // smem row stride in floats -> conflict-free frag LDS

__global__ __launch_bounds__(256, 2) void gemm_mma(
    const float* __restrict__ A, const float* __restrict__ Bt,
    const float* __restrict__ bias, const float* __restrict__ Res,
    float* __restrict__ C, int rnd)
{
    __shared__ uint32_t As[128 * GSTRIDE];
    __shared__ uint32_t Bs[128 * GSTRIDE];

    const int tid  = threadIdx.x;
    const int wid  = tid >> 5;
    const int lane = tid & 31;
    const int wm = wid & 1;
    const int wn = wid >> 1;
    const int qr = lane >> 2;
    const int ql = lane & 3;

    const int row0 = blockIdx.y * 128;
    const int col0 = blockIdx.x * 128;

    float acc[4][4][4];
#pragma unroll
    for (int i = 0; i < 4; i++)
#pragma unroll
        for (int j = 0; j < 4; j++)
#pragma unroll
            for (int r = 0; r < 4; r++) acc[i][j][r] = 0.f;

    int fr[4], fc[4];
    const float* Aptr[4]; const float* Bptr[4];
#pragma unroll
    for (int i = 0; i < 4; i++) {
        int f = i * 256 + tid;
        fr[i] = f >> 3;
        fc[i] = (f & 7) * 4;
        Aptr[i] = A  + (size_t)(row0 + fr[i]) * D_ + fc[i];
        Bptr[i] = Bt + (size_t)(col0 + fr[i]) * D_ + fc[i];
    }

    float4 pa[4], pb[4];
#pragma unroll
    for (int i = 0; i < 4; i++) {
        pa[i] = *(const float4*)(Aptr[i]);
        pb[i] = *(const float4*)(Bptr[i]);
    }

    const int mb0 = wm * 64;
    const int nb0 = wn * 32;

    for (int c = 0; c < D_ / 32; ++c) {
#pragma unroll
        for (int i = 0; i < 4; i++) {
            *(uint4*)&As[fr[i] * GSTRIDE + fc[i]] = *(uint4*)&pa[i];
            *(uint4*)&Bs[fr[i] * GSTRIDE + fc[i]] = *(uint4*)&pb[i];
        }
        __syncthreads();

        if (c + 1 < D_ / 32) {
            const int k0 = (c + 1) * 32;
#pragma unroll
            for (int i = 0; i < 4; i++) {
                pa[i] = *(const float4*)(Aptr[i] + k0);
                pb[i] = *(const float4*)(Bptr[i] + k0);
            }
        }

#pragma unroll
        for (int ks = 0; ks < 4; ++ks) {
            uint32_t af[4][4], bf[4][2];
#pragma unroll
            for (int mt = 0; mt < 4; ++mt) {
                int rbase = (mb0 + mt * 16 + qr) * GSTRIDE + ks * 8 + ql;
                af[mt][0] = As[rbase];
                af[mt][1] = As[rbase + 8 * GSTRIDE];
                af[mt][2] = As[rbase + 4];
                af[mt][3] = As[rbase + 8 * GSTRIDE + 4];
            }
#pragma unroll
            for (int nt = 0; nt < 4; ++nt) {
                int rbase = (nb0 + nt * 8 + qr) * GSTRIDE + ks * 8 + ql;
                bf[nt][0] = Bs[rbase];
                bf[nt][1] = Bs[rbase + 4];
            }
#pragma unroll
            for (int mt = 0; mt < 4; ++mt)
#pragma unroll
                for (int nt = 0; nt < 4; ++nt)
                    mma_tf32(acc[mt][nt], af[mt], bf[nt]);
        }
        __syncthreads();
    }

#pragma unroll
    for (int mt = 0; mt < 4; ++mt) {
        int row_lo = row0 + mb0 + mt * 16 + qr;
#pragma unroll
        for (int nt = 0; nt < 4; ++nt) {
            int col = col0 + nb0 + nt * 8 + ql * 2;
            float2 bb = *(const float2*)&bias[col];
            size_t off_lo = (size_t)row_lo * D_ + col;
            size_t off_hi = off_lo + (size_t)8 * D_;
            float2 o_lo, o_hi;
            o_lo.x = acc[mt][nt][0] + bb.x;
            o_lo.y = acc[mt][nt][1] + bb.y;
            o_hi.x = acc[mt][nt][2] + bb.x;
            o_hi.y = acc[mt][nt][3] + bb.y;
            if (Res) {
                float2 r0 = *(const float2*)&Res[off_lo];
                float2 r1 = *(const float2*)&Res[off_hi];
                o_lo.x += r0.x; o_lo.y += r0.y;
                o_hi.x += r1.x; o_hi.y += r1.y;
            }
            if (rnd) {
                o_lo.x = tf32r(o_lo.x); o_lo.y = tf32r(o_lo.y);
                o_hi.x = tf32r(o_hi.x); o_hi.y = tf32r(o_hi.y);
            }
            *(float2*)&C[off_lo] = o_lo;
            *(float2*)&C[off_hi] = o_hi;
        }
    }
}

// ================ flash attention via tf32 mma.sync ========================
// Round-8 proven configuration (measured ~60us faster than R7's):
// Block: one (b,h), 128 query rows. 8 warps x 16 rows. KV tiles of 128 keys,
// double-buffered cp.async.
// K buffer stride 72 (== 8 mod 32): k-permuted float2 fragment loads for the
// S-phase, conflict-free.  V buffer stride 68: the PV scalar-load pattern is
// conflict-free at 68 (2-way at 72).
// P@V uses the key-permutation trick: S-acc regs (c0,c2,c1,c3) form the A
// fragment directly when V's B-fragment reads keys (2ql, 2ql+1).
#define KST 72
#define VST 68
#define KTS (128 * KST)
#define VTS (128 * VST)

__global__ __launch_bounds__(256) void attn_mma(
    const float* __restrict__ Q, const float* __restrict__ K,
    const float* __restrict__ V, float* __restrict__ O)
{
    extern __shared__ float smf[];
    // layout: K0, V0, K1, V1
    float* kbuf[2] = { smf, smf + KTS + VTS };
    float* vbuf[2] = { smf + KTS, smf + 2 * KTS + VTS };

    const int bz = blockIdx.z, h = blockIdx.y;
    const int q0 = blockIdx.x * 128;
    const int tid = threadIdx.x, wid = tid >> 5, lane = tid & 31;
    const int qr = lane >> 2, ql = lane & 3;
    const int mrow = wid * 16;

    const float* Qg = Q + (((size_t)bz * L_ + q0) * H_ + h) * KD_;
    const float* Kg = K + (((size_t)bz * L_) * H_ + h) * KD_;
    const float* Vg = V + (((size_t)bz * L_) * H_ + h) * KD_;

    // ---- stage Q through kbuf[0], build pre-scaled k-permuted A frags ----
#pragma unroll
    for (int i = 0; i < 8; ++i) {
        int f = i * 256 + tid;
        int r = f >> 4, c4 = f & 15;
        *(float4*)&kbuf[0][r * KST + c4 * 4] =
            *(const float4*)(Qg + (size_t)r * (H_ * KD_) + c4 * 4);
    }
    __syncthreads();
    uint32_t qf[8][4];
#pragma unroll
    for (int ks = 0; ks < 8; ++ks) {
        int cl = ks * 8 + 2 * ql;
        qf[ks][0] = __float_as_uint(0.125f * kbuf[0][(mrow + qr) * KST + cl]);
        qf[ks][1] = __float_as_uint(0.125f * kbuf[0][(mrow + qr + 8) * KST + cl]);
        qf[ks][2] = __float_as_uint(0.125f * kbuf[0][(mrow + qr) * KST + cl + 1]);
        qf[ks][3] = __float_as_uint(0.125f * kbuf[0][(mrow + qr + 8) * KST + cl + 1]);
    }
    __syncthreads();

    float oacc[8][4];
#pragma unroll
    for (int nt = 0; nt < 8; ++nt)
#pragma unroll
        for (int r = 0; r < 4; ++r) oacc[nt][r] = 0.f;
    float m0 = -INFINITY, m1 = -INFINITY, l0 = 0.f, l1 = 0.f;

    // per-thread load slots (8 x float4 per operand per tile)
    int lr[8], lc[8];
#pragma unroll
    for (int i = 0; i < 8; ++i) {
        int f = i * 256 + tid;
        lr[i] = f >> 4;
        lc[i] = (f & 15) * 4;
    }

    // preload tile 0
    {
        uint32_t kd = smem_u32(kbuf[0]);
        uint32_t vd = smem_u32(vbuf[0]);
#pragma unroll
        for (int i = 0; i < 8; ++i) {
            size_t goff = (size_t)lr[i] * (H_ * KD_) + lc[i];
            CP_ASYNC16(kd + (uint32_t)(lr[i] * KST + lc[i]) * 4u, Kg + goff);
            CP_ASYNC16(vd + (uint32_t)(lr[i] * VST + lc[i]) * 4u, Vg + goff);
        }
        CP_COMMIT();
    }

    const int NT = L_ / 128;     // 16 kv tiles
    for (int t = 0; t < NT; ++t) {
        CP_WAIT_ALL();
        __syncthreads();
        if (t + 1 < NT) {
            const int nb = (t + 1) & 1;
            uint32_t kd = smem_u32(kbuf[nb]);
            uint32_t vd = smem_u32(vbuf[nb]);
            const float* Kn = Kg + (size_t)(t + 1) * 128 * (H_ * KD_);
            const float* Vn = Vg + (size_t)(t + 1) * 128 * (H_ * KD_);
#pragma unroll
            for (int i = 0; i < 8; ++i) {
                size_t goff = (size_t)lr[i] * (H_ * KD_) + lc[i];
                CP_ASYNC16(kd + (uint32_t)(lr[i] * KST + lc[i]) * 4u, Kn + goff);
                CP_ASYNC16(vd + (uint32_t)(lr[i] * VST + lc[i]) * 4u, Vn + goff);
            }
            CP_COMMIT();
        }
        const float* Kc = kbuf[t & 1];
        const float* Vc = vbuf[t & 1];

        // ---- S = (Q/8) @ K^T : 16 n-tiles of 8 keys, float2 B frags ----
        float sacc[16][4];
#pragma unroll
        for (int nt = 0; nt < 16; ++nt)
#pragma unroll
            for (int r = 0; r < 4; ++r) sacc[nt][r] = 0.f;
#pragma unroll
        for (int ks = 0; ks < 8; ++ks) {
#pragma unroll
            for (int nt = 0; nt < 16; ++nt) {
                int rb = (nt * 8 + qr) * KST + ks * 8 + 2 * ql;
                float2 b = *(const float2*)&Kc[rb];     // d = 2ql, 2ql+1
                mma_tf32_4(sacc[nt], qf[ks][0], qf[ks][1], qf[ks][2], qf[ks][3],
                           __float_as_uint(b.x), __float_as_uint(b.y));
            }
        }

        // ---- online softmax ----
        float tm0 = -INFINITY, tm1 = -INFINITY;
#pragma unroll
        for (int nt = 0; nt < 16; ++nt) {
            tm0 = fmaxf(tm0, fmaxf(sacc[nt][0], sacc[nt][1]));
            tm1 = fmaxf(tm1, fmaxf(sacc[nt][2], sacc[nt][3]));
        }
        tm0 = fmaxf(tm0, __shfl_xor_sync(0xffffffff, tm0, 1));
        tm0 = fmaxf(tm0, __shfl_xor_sync(0xffffffff, tm0, 2));
        tm1 = fmaxf(tm1, __shfl_xor_sync(0xffffffff, tm1, 1));
        tm1 = fmaxf(tm1, __shfl_xor_sync(0xffffffff, tm1, 2));

        float mn0 = fmaxf(m0, tm0), mn1 = fmaxf(m1, tm1);
        float c0 = __expf(m0 - mn0), c1 = __expf(m1 - mn1);
        l0 *= c0; l1 *= c1;
#pragma unroll
        for (int nt = 0; nt < 8; ++nt) {
            oacc[nt][0] *= c0; oacc[nt][1] *= c0;
            oacc[nt][2] *= c1; oacc[nt][3] *= c1;
        }
        m0 = mn0; m1 = mn1;

#pragma unroll
        for (int nt = 0; nt < 16; ++nt) {
            float p0 = __expf(sacc[nt][0] - m0);
            float p1 = __expf(sacc[nt][1] - m0);
            float p2 = __expf(sacc[nt][2] - m1);
            float p3 = __expf(sacc[nt][3] - m1);
            l0 += p0 + p1;
            l1 += p2 + p3;
            sacc[nt][0] = tf32r(p0);
            sacc[nt][1] = tf32r(p1);
            sacc[nt][2] = tf32r(p2);
            sacc[nt][3] = tf32r(p3);
        }

        // ---- O += P @ V (key-permuted B fragments) ----
#pragma unroll
        for (int g = 0; g < 16; ++g) {
            uint32_t a0 = __float_as_uint(sacc[g][0]);
            uint32_t a1 = __float_as_uint(sacc[g][2]);
            uint32_t a2 = __float_as_uint(sacc[g][1]);
            uint32_t a3 = __float_as_uint(sacc[g][3]);
#pragma unroll
            for (int nt = 0; nt < 8; ++nt) {
                uint32_t b0 = __float_as_uint(Vc[(g * 8 + 2 * ql) * VST + nt * 8 + qr]);
                uint32_t b1 = __float_as_uint(Vc[(g * 8 + 2 * ql + 1) * VST + nt * 8 + qr]);
                mma_tf32_4(oacc[nt], a0, a1, a2, a3, b0, b1);
            }
        }
    }

    // reduce the softmax denominator across the thread quad (each thread's l
    // only covers score columns (2ql, 2ql+1) of each 8-tile; oacc covers all)
    l0 += __shfl_xor_sync(0xffffffff, l0, 1);
    l0 += __shfl_xor_sync(0xffffffff, l0, 2);
    l1 += __shfl_xor_sync(0xffffffff, l1, 1);
    l1 += __shfl_xor_sync(0xffffffff, l1, 2);

    // ---- normalize + store (tf32-rounded for the Wo GEMM) ----
    float inv0 = 1.f / l0, inv1 = 1.f / l1;
    const int row_lo = q0 + mrow + qr;
    const int row_hi = row_lo + 8;
#pragma unroll
    for (int nt = 0; nt < 8; ++nt) {
        int d = nt * 8 + 2 * ql;
        float2 vlo, vhi;
        vlo.x = tf32r(oacc[nt][0] * inv0);
        vlo.y = tf32r(oacc[nt][1] * inv0);
        vhi.x = tf32r(oacc[nt][2] * inv1);
        vhi.y = tf32r(oacc[nt][3] * inv1);
        *(float2*)&O[(((size_t)bz * L_ + row_lo) * H_ + h) * KD_ + d] = vlo;
        *(float2*)&O[(((size_t)bz * L_ + row_hi) * H_ + h) * KD_ + d] = vhi;
    }
}

// ---------------- elementwise tf32 rounding pass ---------------------------
__global__ __launch_bounds__(256) void round_tf32_kernel(
    const float* __restrict__ X, float* __restrict__ Y)
{
    int i = blockIdx.x * 256 + threadIdx.x;
    float4 v = ((const float4*)X)[i];
    float4 o;
    o.x = tf32r(v.x); o.y = tf32r(v.y); o.z = tf32r(v.z); o.w = tf32r(v.w);
    ((float4*)Y)[i] = o;
}

// ---------------- weight transpose + tf32 round ----------------------------
__global__ __launch_bounds__(256) void transpose4(
    const float* __restrict__ W0, const float* __restrict__ W1,
    const float* __restrict__ W2, const float* __restrict__ W3,
    float* __restrict__ T0, float* __restrict__ T1,
    float* __restrict__ T2, float* __restrict__ T3)
{
    __shared__ float tile[32][33];
    const float* W; float* T;
    switch (blockIdx.z) {
        case 0: W = W0; T = T0; break;
        case 1: W = W1; T = T1; break;
        case 2: W = W2; T = T2; break;
        default: W = W3; T = T3; break;
    }
    int tx = threadIdx.x, ty = threadIdx.y;
    int x = blockIdx.x * 32 + tx;
    int y = blockIdx.y * 32 + ty;
#pragma unroll
    for (int i = 0; i < 4; ++i)
        tile[ty + 8 * i][tx] = W[(size_t)(y + 8 * i) * D_ + x];
    __syncthreads();
    int x2 = blockIdx.y * 32 + tx;
    int y2 = blockIdx.x * 32 + ty;
#pragma unroll
    for (int i = 0; i < 4; ++i)
        T[(size_t)(y2 + 8 * i) * D_ + x2] = tf32r(tile[tx][ty + 8 * i]);
}

// ---------------- LayerNorm: one block per row -----------------------------
__global__ __launch_bounds__(256) void ln_kernel(
    const float* __restrict__ X, const float* __restrict__ gamma,
    const float* __restrict__ beta, float* __restrict__ Y)
{
    const int row = blockIdx.x;
    const int tid = threadIdx.x;
    const float4* x = (const float4*)(X + (size_t)row * D_);
    float4 v = x[tid];

    float s  = v.x + v.y + v.z + v.w;
    float sq = v.x * v.x + v.y * v.y + v.z * v.z + v.w * v.w;
#pragma unroll
    for (int off = 16; off > 0; off >>= 1) {
        s  += __shfl_xor_sync(0xffffffff, s, off);
        sq += __shfl_xor_sync(0xffffffff, sq, off);
    }
    __shared__ float2 red[8];
    if ((tid & 31) == 0) red[tid >> 5] = make_float2(s, sq);
    __syncthreads();
    if (tid < 8) {
        float2 r = red[tid];
#pragma unroll
        for (int off = 4; off > 0; off >>= 1) {
            r.x += __shfl_xor_sync(0xff, r.x, off);
            r.y += __shfl_xor_sync(0xff, r.y, off);
        }
        if (tid == 0) red[0] = r;
    }
    __syncthreads();
    float mean = red[0].x * (1.f / D_);
    float var  = red[0].y * (1.f / D_) - mean * mean;
    float rstd = rsqrtf(var + EPS_);

    float4 g = ((const float4*)gamma)[tid];
    float4 bt = ((const float4*)beta)[tid];
    float4 o;
    o.x = (v.x - mean) * rstd * g.x + bt.x;
    o.y = (v.y - mean) * rstd * g.y + bt.y;
    o.z = (v.z - mean) * rstd * g.z + bt.z;
    o.w = (v.w - mean) * rstd * g.w + bt.w;
    ((float4*)(Y + (size_t)row * D_))[tid] = o;
}

// ---------------- host launch ----------------------------------------------
#define ATTN_SMEM (2 * (KTS + VTS) * 4)   // 143360 bytes

extern "C" void kernel_launch(void* const* d_in, const int* in_sizes, int n_in,
                              void* d_out, int out_size)
{
    const float* queries = (const float*)d_in[0];
    const float* Wq = (const float*)d_in[1];
    const float* bq = (const float*)d_in[2];
    const float* Wk = (const float*)d_in[3];
    const float* bk = (const float*)d_in[4];
    const float* Wv = (const float*)d_in[5];
    const float* bv = (const float*)d_in[6];
    const float* Wo = (const float*)d_in[7];
    const float* bo = (const float*)d_in[8];
    const float* gamma = (const float*)d_in[9];
    const float* beta  = (const float*)d_in[10];

    float *q, *k, *v, *o, *res, *qr, *wqt, *wkt, *wvt, *wot;
    cudaGetSymbolAddress((void**)&q,   g_q);
    cudaGetSymbolAddress((void**)&k,   g_k);
    cudaGetSymbolAddress((void**)&v,   g_v);
    cudaGetSymbolAddress((void**)&o,   g_o);
    cudaGetSymbolAddress((void**)&res, g_res);
    cudaGetSymbolAddress((void**)&qr,  g_qr);
    cudaGetSymbolAddress((void**)&wqt, g_wqt);
    cudaGetSymbolAddress((void**)&wkt, g_wkt);
    cudaGetSymbolAddress((void**)&wvt, g_wvt);
    cudaGetSymbolAddress((void**)&wot, g_wot);

    cudaFuncSetAttribute(attn_mma, cudaFuncAttributeMaxDynamicSharedMemorySize,
                         ATTN_SMEM);

    round_tf32_kernel<<<(M_ * D_) / (256 * 4), 256>>>(queries, qr);
    transpose4<<<dim3(32, 32, 4), dim3(32, 8)>>>(Wq, Wk, Wv, Wo, wqt, wkt, wvt, wot);

    dim3 gGrid(D_ / 128, M_ / 128);   // (8, 64)
    gemm_mma<<<gGrid, 256>>>(qr, wqt, bq, nullptr, q, 1);
    gemm_mma<<<gGrid, 256>>>(qr, wkt, bk, nullptr, k, 1);
    gemm_mma<<<gGrid, 256>>>(qr, wvt, bv, nullptr, v, 1);

    attn_mma<<<dim3(L_ / 128, H_, B_), 256, ATTN_SMEM>>>(q, k, v, o);

    gemm_mma<<<gGrid, 256>>>(o, wot, bo, queries, res, 0);

    ln_kernel<<<M_, 256>>>(res, gamma, beta, (float*)d_out);
}

// round 13
// speedup vs baseline: 1.1095x; 1.0097x over previous
#include <cuda_runtime.h>
#include <cuda_bf16.h>
#include <math.h>
#include <stdint.h>

// Problem constants
#define B_  4
#define L_  2048
#define D_  1024
#define H_  16
#define KD_ 64
#define M_  (B_ * L_)        // 8192 token rows
#define EPS_ 1e-5f

// ---------------- scratch (device globals; no allocation allowed) ----------
__device__ float g_q[M_ * D_];
__device__ float g_k[M_ * D_];
__device__ float g_v[M_ * D_];
__device__ float g_o[M_ * D_];
__device__ float g_res[M_ * D_];
__device__ float g_qr[M_ * D_];     // tf32-rounded copy of queries (MMA operand)
__device__ float g_wqt[D_ * D_];
__device__ float g_wkt[D_ * D_];
__device__ float g_wvt[D_ * D_];
__device__ float g_wot[D_ * D_];

// ---------------- helpers ---------------------------------------------------
__device__ __forceinline__ float tf32r(float x) {
    uint32_t u;
    asm("cvt.rna.tf32.f32 %0, %1;" : "=r"(u) : "f"(x));
    return __uint_as_float(u);
}

__device__ __forceinline__ void mma_tf32_4(float* d,
    uint32_t a0, uint32_t a1, uint32_t a2, uint32_t a3,
    uint32_t b0, uint32_t b1) {
    asm volatile(
        "mma.sync.aligned.m16n8k8.row.col.f32.tf32.tf32.f32 "
        "{%0,%1,%2,%3}, {%4,%5,%6,%7}, {%8,%9}, {%0,%1,%2,%3};\n"
        : "+f"(d[0]), "+f"(d[1]), "+f"(d[2]), "+f"(d[3])
        : "r"(a0), "r"(a1), "r"(a2), "r"(a3), "r"(b0), "r"(b1));
}

__device__ __forceinline__ uint32_t smem_u32(const void* p) {
    uint32_t a;
    asm("{ .reg .u64 t; cvta.to.shared.u64 t, %1; cvt.u32.u64 %0, t; }"
        : "=r"(a) : "l"(p));
    return a;
}
#define CP_ASYNC16(dst_u32, src_ptr) \
    asm volatile("cp.async.cg.shared.global [%0], [%1], 16;" \
        :: "r"(dst_u32), "l"(src_ptr))
#define CP_COMMIT() asm volatile("cp.async.commit_group;" ::: "memory")
#define CP_WAIT_ALL() asm volatile("cp.async.wait_all;" ::: "memory")

// ================= tf32 warp-MMA GEMM ======================================
// C[8192,1024] = A@Bt^T + bias (+Res).  Tile 128x128, BK=32, 8 warps (2x4).
// k-permuted float2 fragment loads (LDS.64): within each k8 block a thread's
// register pair holds contraction indices (2ql, 2ql+1) for BOTH operands.
// Stride 40 == 8 (mod 32): banks (8*qr + 2*ql) % 32 distinct per 16-lane
// phase -> conflict-free.  __launch_bounds__(256,2) pins 2 CTAs/SM (the R8
// regression was ptxas drifting to 142 regs -> 1 CTA/SM; the pin removes
// that confound).
#define GSTRIDE 40   // smem row stride in floats

__global__ __launch_bounds__(256, 2) void gemm_mma(
    const float* __restrict__ A, const float* __restrict__ Bt,
    const float* __restrict__ bias, const float* __restrict__ Res,
    float* __restrict__ C, int rnd)
{
    __shared__ __align__(16) float As[128 * GSTRIDE];
    __shared__ __align__(16) float Bs[128 * GSTRIDE];

    const int tid  = threadIdx.x;
    const int wid  = tid >> 5;
    const int lane = tid & 31;
    const int wm = wid & 1;
    const int wn = wid >> 1;
    const int qr = lane >> 2;
    const int ql = lane & 3;

    const int row0 = blockIdx.y * 128;
    const int col0 = blockIdx.x * 128;

    float acc[4][4][4];
#pragma unroll
    for (int i = 0; i < 4; i++)
#pragma unroll
        for (int j = 0; j < 4; j++)
#pragma unroll
            for (int r = 0; r < 4; r++) acc[i][j][r] = 0.f;

    int fr[4], fc[4];
    const float* Aptr[4]; const float* Bptr[4];
#pragma unroll
    for (int i = 0; i < 4; i++) {
        int f = i * 256 + tid;
        fr[i] = f >> 3;
        fc[i] = (f & 7) * 4;
        Aptr[i] = A  + (size_t)(row0 + fr[i]) * D_ + fc[i];
        Bptr[i] = Bt + (size_t)(col0 + fr[i]) * D_ + fc[i];
    }

    float4 pa[4], pb[4];
#pragma unroll
    for (int i = 0; i < 4; i++) {
        pa[i] = *(const float4*)(Aptr[i]);
        pb[i] = *(const float4*)(Bptr[i]);
    }

    const int mb0 = wm * 64;
    const int nb0 = wn * 32;

    for (int c = 0; c < D_ / 32; ++c) {
#pragma unroll
        for (int i = 0; i < 4; i++) {
            *(float4*)&As[fr[i] * GSTRIDE + fc[i]] = pa[i];
            *(float4*)&Bs[fr[i] * GSTRIDE + fc[i]] = pb[i];
        }
        __syncthreads();

        if (c + 1 < D_ / 32) {
            const int k0 = (c + 1) * 32;
#pragma unroll
            for (int i = 0; i < 4; i++) {
                pa[i] = *(const float4*)(Aptr[i] + k0);
                pb[i] = *(const float4*)(Bptr[i] + k0);
            }
        }

#pragma unroll
        for (int ks = 0; ks < 4; ++ks) {
            uint32_t af[4][4], bf[4][2];
#pragma unroll
            for (int mt = 0; mt < 4; ++mt) {
                int rb = (mb0 + mt * 16 + qr) * GSTRIDE + ks * 8 + 2 * ql;
                float2 lo = *(const float2*)&As[rb];                 // k = 2ql, 2ql+1
                float2 hi = *(const float2*)&As[rb + 8 * GSTRIDE];
                af[mt][0] = __float_as_uint(lo.x);
                af[mt][2] = __float_as_uint(lo.y);
                af[mt][1] = __float_as_uint(hi.x);
                af[mt][3] = __float_as_uint(hi.y);
            }
#pragma unroll
            for (int nt = 0; nt < 4; ++nt) {
                int rb = (nb0 + nt * 8 + qr) * GSTRIDE + ks * 8 + 2 * ql;
                float2 b = *(const float2*)&Bs[rb];
                bf[nt][0] = __float_as_uint(b.x);
                bf[nt][1] = __float_as_uint(b.y);
            }
#pragma unroll
            for (int mt = 0; mt < 4; ++mt)
#pragma unroll
                for (int nt = 0; nt < 4; ++nt)
                    mma_tf32_4(acc[mt][nt], af[mt][0], af[mt][1], af[mt][2], af[mt][3],
                               bf[nt][0], bf[nt][1]);
        }
        __syncthreads();
    }

#pragma unroll
    for (int mt = 0; mt < 4; ++mt) {
        int row_lo = row0 + mb0 + mt * 16 + qr;
#pragma unroll
        for (int nt = 0; nt < 4; ++nt) {
            int col = col0 + nb0 + nt * 8 + ql * 2;
            float2 bb = *(const float2*)&bias[col];
            size_t off_lo = (size_t)row_lo * D_ + col;
            size_t off_hi = off_lo + (size_t)8 * D_;
            float2 o_lo, o_hi;
            o_lo.x = acc[mt][nt][0] + bb.x;
            o_lo.y = acc[mt][nt][1] + bb.y;
            o_hi.x = acc[mt][nt][2] + bb.x;
            o_hi.y = acc[mt][nt][3] + bb.y;
            if (Res) {
                float2 r0 = *(const float2*)&Res[off_lo];
                float2 r1 = *(const float2*)&Res[off_hi];
                o_lo.x += r0.x; o_lo.y += r0.y;
                o_hi.x += r1.x; o_hi.y += r1.y;
            }
            if (rnd) {
                o_lo.x = tf32r(o_lo.x); o_lo.y = tf32r(o_lo.y);
                o_hi.x = tf32r(o_hi.x); o_hi.y = tf32r(o_hi.y);
            }
            *(float2*)&C[off_lo] = o_lo;
            *(float2*)&C[off_hi] = o_hi;
        }
    }
}

// ================ flash attention via tf32 mma.sync ========================
// Block: one (b,h), 128 query rows. 8 warps x 16 rows. KV tiles of 128 keys,
// double-buffered cp.async.  K stride 72 (float2 k-permuted S frags), V
// stride 68 (scalar PV loads conflict-free there).
// Softmax in the exp2 domain: Q frags pre-scaled by 0.125*log2(e), so
// p = exp2f(s - m) — one EX2, no FMUL.  P and the O store are fed to the
// MMA as raw fp32 (HW truncates to tf32; error ~2^-11, far under budget).
#define KST 72
#define VST 68
#define KTS (128 * KST)
#define VTS (128 * VST)
#define QSCALE 0.1803368809f   // 0.125 * log2(e)

__global__ __launch_bounds__(256) void attn_mma(
    const float* __restrict__ Q, const float* __restrict__ K,
    const float* __restrict__ V, float* __restrict__ O)
{
    extern __shared__ float smf[];
    // layout: K0, V0, K1, V1
    float* kbuf[2] = { smf, smf + KTS + VTS };
    float* vbuf[2] = { smf + KTS, smf + 2 * KTS + VTS };

    const int bz = blockIdx.z, h = blockIdx.y;
    const int q0 = blockIdx.x * 128;
    const int tid = threadIdx.x, wid = tid >> 5, lane = tid & 31;
    const int qr = lane >> 2, ql = lane & 3;
    const int mrow = wid * 16;

    const float* Qg = Q + (((size_t)bz * L_ + q0) * H_ + h) * KD_;
    const float* Kg = K + (((size_t)bz * L_) * H_ + h) * KD_;
    const float* Vg = V + (((size_t)bz * L_) * H_ + h) * KD_;

    // ---- stage Q through kbuf[0], build pre-scaled k-permuted A frags ----
#pragma unroll
    for (int i = 0; i < 8; ++i) {
        int f = i * 256 + tid;
        int r = f >> 4, c4 = f & 15;
        *(float4*)&kbuf[0][r * KST + c4 * 4] =
            *(const float4*)(Qg + (size_t)r * (H_ * KD_) + c4 * 4);
    }
    __syncthreads();
    uint32_t qf[8][4];
#pragma unroll
    for (int ks = 0; ks < 8; ++ks) {
        int cl = ks * 8 + 2 * ql;
        qf[ks][0] = __float_as_uint(QSCALE * kbuf[0][(mrow + qr) * KST + cl]);
        qf[ks][1] = __float_as_uint(QSCALE * kbuf[0][(mrow + qr + 8) * KST + cl]);
        qf[ks][2] = __float_as_uint(QSCALE * kbuf[0][(mrow + qr) * KST + cl + 1]);
        qf[ks][3] = __float_as_uint(QSCALE * kbuf[0][(mrow + qr + 8) * KST + cl + 1]);
    }
    __syncthreads();

    float oacc[8][4];
#pragma unroll
    for (int nt = 0; nt < 8; ++nt)
#pragma unroll
        for (int r = 0; r < 4; ++r) oacc[nt][r] = 0.f;
    float m0 = -INFINITY, m1 = -INFINITY, l0 = 0.f, l1 = 0.f;

    // per-thread load slots (8 x float4 per operand per tile)
    int lr[8], lc[8];
#pragma unroll
    for (int i = 0; i < 8; ++i) {
        int f = i * 256 + tid;
        lr[i] = f >> 4;
        lc[i] = (f & 15) * 4;
    }

    // preload tile 0
    {
        uint32_t kd = smem_u32(kbuf[0]);
        uint32_t vd = smem_u32(vbuf[0]);
#pragma unroll
        for (int i = 0; i < 8; ++i) {
            size_t goff = (size_t)lr[i] * (H_ * KD_) + lc[i];
            CP_ASYNC16(kd + (uint32_t)(lr[i] * KST + lc[i]) * 4u, Kg + goff);
            CP_ASYNC16(vd + (uint32_t)(lr[i] * VST + lc[i]) * 4u, Vg + goff);
        }
        CP_COMMIT();
    }

    const int NT = L_ / 128;     // 16 kv tiles
    for (int t = 0; t < NT; ++t) {
        CP_WAIT_ALL();
        __syncthreads();
        if (t + 1 < NT) {
            const int nb = (t + 1) & 1;
            uint32_t kd = smem_u32(kbuf[nb]);
            uint32_t vd = smem_u32(vbuf[nb]);
            const float* Kn = Kg + (size_t)(t + 1) * 128 * (H_ * KD_);
            const float* Vn = Vg + (size_t)(t + 1) * 128 * (H_ * KD_);
#pragma unroll
            for (int i = 0; i < 8; ++i) {
                size_t goff = (size_t)lr[i] * (H_ * KD_) + lc[i];
                CP_ASYNC16(kd + (uint32_t)(lr[i] * KST + lc[i]) * 4u, Kn + goff);
                CP_ASYNC16(vd + (uint32_t)(lr[i] * VST + lc[i]) * 4u, Vn + goff);
            }
            CP_COMMIT();
        }
        const float* Kc = kbuf[t & 1];
        const float* Vc = vbuf[t & 1];

        // ---- S = (Q*scale) @ K^T : 16 n-tiles of 8 keys, float2 B frags ----
        float sacc[16][4];
#pragma unroll
        for (int nt = 0; nt < 16; ++nt)
#pragma unroll
            for (int r = 0; r < 4; ++r) sacc[nt][r] = 0.f;
#pragma unroll
        for (int ks = 0; ks < 8; ++ks) {
#pragma unroll
            for (int nt = 0; nt < 16; ++nt) {
                int rb = (nt * 8 + qr) * KST + ks * 8 + 2 * ql;
                float2 b = *(const float2*)&Kc[rb];     // d = 2ql, 2ql+1
                mma_tf32_4(sacc[nt], qf[ks][0], qf[ks][1], qf[ks][2], qf[ks][3],
                           __float_as_uint(b.x), __float_as_uint(b.y));
            }
        }

        // ---- online softmax (log2 domain) ----
        float tm0 = -INFINITY, tm1 = -INFINITY;
#pragma unroll
        for (int nt = 0; nt < 16; ++nt) {
            tm0 = fmaxf(tm0, fmaxf(sacc[nt][0], sacc[nt][1]));
            tm1 = fmaxf(tm1, fmaxf(sacc[nt][2], sacc[nt][3]));
        }
        tm0 = fmaxf(tm0, __shfl_xor_sync(0xffffffff, tm0, 1));
        tm0 = fmaxf(tm0, __shfl_xor_sync(0xffffffff, tm0, 2));
        tm1 = fmaxf(tm1, __shfl_xor_sync(0xffffffff, tm1, 1));
        tm1 = fmaxf(tm1, __shfl_xor_sync(0xffffffff, tm1, 2));

        float mn0 = fmaxf(m0, tm0), mn1 = fmaxf(m1, tm1);
        float c0 = exp2f(m0 - mn0), c1 = exp2f(m1 - mn1);
        l0 *= c0; l1 *= c1;
#pragma unroll
        for (int nt = 0; nt < 8; ++nt) {
            oacc[nt][0] *= c0; oacc[nt][1] *= c0;
            oacc[nt][2] *= c1; oacc[nt][3] *= c1;
        }
        m0 = mn0; m1 = mn1;

#pragma unroll
        for (int nt = 0; nt < 16; ++nt) {
            float p0 = exp2f(sacc[nt][0] - m0);
            float p1 = exp2f(sacc[nt][1] - m0);
            float p2 = exp2f(sacc[nt][2] - m1);
            float p3 = exp2f(sacc[nt][3] - m1);
            l0 += p0 + p1;
            l1 += p2 + p3;
            sacc[nt][0] = p0;   // raw fp32 -> MMA truncates to tf32
            sacc[nt][1] = p1;
            sacc[nt][2] = p2;
            sacc[nt][3] = p3;
        }

        // ---- O += P @ V (key-permuted B fragments) ----
#pragma unroll
        for (int g = 0; g < 16; ++g) {
            uint32_t a0 = __float_as_uint(sacc[g][0]);
            uint32_t a1 = __float_as_uint(sacc[g][2]);
            uint32_t a2 = __float_as_uint(sacc[g][1]);
            uint32_t a3 = __float_as_uint(sacc[g][3]);
#pragma unroll
            for (int nt = 0; nt < 8; ++nt) {
                uint32_t b0 = __float_as_uint(Vc[(g * 8 + 2 * ql) * VST + nt * 8 + qr]);
                uint32_t b1 = __float_as_uint(Vc[(g * 8 + 2 * ql + 1) * VST + nt * 8 + qr]);
                mma_tf32_4(oacc[nt], a0, a1, a2, a3, b0, b1);
            }
        }
    }

    // reduce the softmax denominator across the thread quad (each thread's l
    // only covers score columns (2ql, 2ql+1) of each 8-tile; oacc covers all)
    l0 += __shfl_xor_sync(0xffffffff, l0, 1);
    l0 += __shfl_xor_sync(0xffffffff, l0, 2);
    l1 += __shfl_xor_sync(0xffffffff, l1, 1);
    l1 += __shfl_xor_sync(0xffffffff, l1, 2);

    // ---- normalize + store (raw fp32; Wo GEMM truncates to tf32) ----
    float inv0 = 1.f / l0, inv1 = 1.f / l1;
    const int row_lo = q0 + mrow + qr;
    const int row_hi = row_lo + 8;
#pragma unroll
    for (int nt = 0; nt < 8; ++nt) {
        int d = nt * 8 + 2 * ql;
        float2 vlo, vhi;
        vlo.x = oacc[nt][0] * inv0;
        vlo.y = oacc[nt][1] * inv0;
        vhi.x = oacc[nt][2] * inv1;
        vhi.y = oacc[nt][3] * inv1;
        *(float2*)&O[(((size_t)bz * L_ + row_lo) * H_ + h) * KD_ + d] = vlo;
        *(float2*)&O[(((size_t)bz * L_ + row_hi) * H_ + h) * KD_ + d] = vhi;
    }
}

// ---------------- elementwise tf32 rounding pass ---------------------------
__global__ __launch_bounds__(256) void round_tf32_kernel(
    const float* __restrict__ X, float* __restrict__ Y)
{
    int i = blockIdx.x * 256 + threadIdx.x;
    float4 v = ((const float4*)X)[i];
    float4 o;
    o.x = tf32r(v.x); o.y = tf32r(v.y); o.z = tf32r(v.z); o.w = tf32r(v.w);
    ((float4*)Y)[i] = o;
}

// ---------------- weight transpose + tf32 round ----------------------------
__global__ __launch_bounds__(256) void transpose4(
    const float* __restrict__ W0, const float* __restrict__ W1,
    const float* __restrict__ W2, const float* __restrict__ W3,
    float* __restrict__ T0, float* __restrict__ T1,
    float* __restrict__ T2, float* __restrict__ T3)
{
    __shared__ float tile[32][33];
    const float* W; float* T;
    switch (blockIdx.z) {
        case 0: W = W0; T = T0; break;
        case 1: W = W1; T = T1; break;
        case 2: W = W2; T = T2; break;
        default: W = W3; T = T3; break;
    }
    int tx = threadIdx.x, ty = threadIdx.y;
    int x = blockIdx.x * 32 + tx;
    int y = blockIdx.y * 32 + ty;
#pragma unroll
    for (int i = 0; i < 4; ++i)
        tile[ty + 8 * i][tx] = W[(size_t)(y + 8 * i) * D_ + x];
    __syncthreads();
    int x2 = blockIdx.y * 32 + tx;
    int y2 = blockIdx.x * 32 + ty;
#pragma unroll
    for (int i = 0; i < 4; ++i)
        T[(size_t)(y2 + 8 * i) * D_ + x2] = tf32r(tile[tx][ty + 8 * i]);
}

// ---------------- LayerNorm: one block per row -----------------------------
__global__ __launch_bounds__(256) void ln_kernel(
    const float* __restrict__ X, const float* __restrict__ gamma,
    const float* __restrict__ beta, float* __restrict__ Y)
{
    const int row = blockIdx.x;
    const int tid = threadIdx.x;
    const float4* x = (const float4*)(X + (size_t)row * D_);
    float4 v = x[tid];

    float s  = v.x + v.y + v.z + v.w;
    float sq = v.x * v.x + v.y * v.y + v.z * v.z + v.w * v.w;
#pragma unroll
    for (int off = 16; off > 0; off >>= 1) {
        s  += __shfl_xor_sync(0xffffffff, s, off);
        sq += __shfl_xor_sync(0xffffffff, sq, off);
    }
    __shared__ float2 red[8];
    if ((tid & 31) == 0) red[tid >> 5] = make_float2(s, sq);
    __syncthreads();
    if (tid < 8) {
        float2 r = red[tid];
#pragma unroll
        for (int off = 4; off > 0; off >>= 1) {
            r.x += __shfl_xor_sync(0xff, r.x, off);
            r.y += __shfl_xor_sync(0xff, r.y, off);
        }
        if (tid == 0) red[0] = r;
    }
    __syncthreads();
    float mean = red[0].x * (1.f / D_);
    float var  = red[0].y * (1.f / D_) - mean * mean;
    float rstd = rsqrtf(var + EPS_);

    float4 g = ((const float4*)gamma)[tid];
    float4 bt = ((const float4*)beta)[tid];
    float4 o;
    o.x = (v.x - mean) * rstd * g.x + bt.x;
    o.y = (v.y - mean) * rstd * g.y + bt.y;
    o.z = (v.z - mean) * rstd * g.z + bt.z;
    o.w = (v.w - mean) * rstd * g.w + bt.w;
    ((float4*)(Y + (size_t)row * D_))[tid] = o;
}

// ---------------- host launch ----------------------------------------------
#define ATTN_SMEM (2 * (KTS + VTS) * 4)   // 143360 bytes

extern "C" void kernel_launch(void* const* d_in, const int* in_sizes, int n_in,
                              void* d_out, int out_size)
{
    const float* queries = (const float*)d_in[0];
    const float* Wq = (const float*)d_in[1];
    const float* bq = (const float*)d_in[2];
    const float* Wk = (const float*)d_in[3];
    const float* bk = (const float*)d_in[4];
    const float* Wv = (const float*)d_in[5];
    const float* bv = (const float*)d_in[6];
    const float* Wo = (const float*)d_in[7];
    const float* bo = (const float*)d_in[8];
    const float* gamma = (const float*)d_in[9];
    const float* beta  = (const float*)d_in[10];

    float *q, *k, *v, *o, *res, *qr, *wqt, *wkt, *wvt, *wot;
    cudaGetSymbolAddress((void**)&q,   g_q);
    cudaGetSymbolAddress((void**)&k,   g_k);
    cudaGetSymbolAddress((void**)&v,   g_v);
    cudaGetSymbolAddress((void**)&o,   g_o);
    cudaGetSymbolAddress((void**)&res, g_res);
    cudaGetSymbolAddress((void**)&qr,  g_qr);
    cudaGetSymbolAddress((void**)&wqt, g_wqt);
    cudaGetSymbolAddress((void**)&wkt, g_wkt);
    cudaGetSymbolAddress((void**)&wvt, g_wvt);
    cudaGetSymbolAddress((void**)&wot, g_wot);

    cudaFuncSetAttribute(attn_mma, cudaFuncAttributeMaxDynamicSharedMemorySize,
                         ATTN_SMEM);

    round_tf32_kernel<<<(M_ * D_) / (256 * 4), 256>>>(queries, qr);
    transpose4<<<dim3(32, 32, 4), dim3(32, 8)>>>(Wq, Wk, Wv, Wo, wqt, wkt, wvt, wot);

    dim3 gGrid(D_ / 128, M_ / 128);   // (8, 64)
    gemm_mma<<<gGrid, 256>>>(qr, wqt, bq, nullptr, q, 1);
    gemm_mma<<<gGrid, 256>>>(qr, wkt, bk, nullptr, k, 1);
    gemm_mma<<<gGrid, 256>>>(qr, wvt, bv, nullptr, v, 1);

    attn_mma<<<dim3(L_ / 128, H_, B_), 256, ATTN_SMEM>>>(q, k, v, o);

    gemm_mma<<<gGrid, 256>>>(o, wot, bo, queries, res, 0);

    ln_kernel<<<M_, 256>>>(res, gamma, beta, (float*)d_out);
}